// round 1
// baseline (speedup 1.0000x reference)
#include <cuda_runtime.h>
#include <cuda_bf16.h>
#include <math.h>

// Problem constants
#define BATCH 8
#define CCH   512            // channels
#define SSP   1024           // H*W
#define NG    8              // groups
#define CPG   64             // channels per group
#define NH    8              // heads
#define HD    64             // head dim
#define THREE_C 1536
#define EPS_GN 1e-5f
#define DT_INL 0.1f

// ---------------------------------------------------------------------------
// Scratch (device globals; allocation-free per harness rules)
// ---------------------------------------------------------------------------
__device__ float g_ht [BATCH * SSP * CCH];        // groupnorm out, [B][S][C]
__device__ float g_qkv[BATCH * THREE_C * SSP];    // qkv, [B][3C][S]
__device__ float g_hf [BATCH * SSP * CCH];        // attention out / INL state [B][S][C]
__device__ float g_y  [BATCH * SSP * CCH];        // INL matmul out [B][S][C]

// ---------------------------------------------------------------------------
// GroupNorm + transpose to [B, S, C]
// grid: B*NG blocks, 256 threads
// ---------------------------------------------------------------------------
__global__ __launch_bounds__(256) void gn_kernel(
    const float* __restrict__ x, const float* __restrict__ scale,
    const float* __restrict__ bias, float* __restrict__ ht)
{
    const int b = blockIdx.x / NG;
    const int g = blockIdx.x % NG;
    const float* xp = x + ((size_t)b * CCH + (size_t)g * CPG) * SSP;
    const int NEL = CPG * SSP;  // 65536

    float s = 0.f, s2 = 0.f;
    for (int i = threadIdx.x; i < NEL; i += 256) {
        float v = xp[i];
        s += v; s2 += v * v;
    }
    // warp reduce
    #pragma unroll
    for (int o = 16; o > 0; o >>= 1) {
        s  += __shfl_down_sync(0xffffffffu, s,  o);
        s2 += __shfl_down_sync(0xffffffffu, s2, o);
    }
    __shared__ float ws[8], ws2[8];
    __shared__ float sh_mean, sh_inv;
    const int wid = threadIdx.x >> 5, lane = threadIdx.x & 31;
    if (lane == 0) { ws[wid] = s; ws2[wid] = s2; }
    __syncthreads();
    if (threadIdx.x == 0) {
        float S = 0.f, S2 = 0.f;
        #pragma unroll
        for (int w = 0; w < 8; w++) { S += ws[w]; S2 += ws2[w]; }
        float mean = S / (float)NEL;
        float var  = S2 / (float)NEL - mean * mean;
        sh_mean = mean;
        sh_inv  = rsqrtf(var + EPS_GN);
    }
    __syncthreads();
    const float mean = sh_mean, inv = sh_inv;

    for (int i = threadIdx.x; i < NEL; i += 256) {
        int c    = g * CPG + (i / SSP);
        int spos = i % SSP;
        float v = (xp[i] - mean) * inv * scale[c] + bias[c];
        ht[((size_t)b * SSP + spos) * CCH + c] = v;
    }
}

// ---------------------------------------------------------------------------
// Generic SGEMM, C[m][n] = sum_k A[m][k]*B[n][k] (+bias[m]) (+resid[m*N+n])
// A: [M,K] row-major, B: [N,K] row-major, C: [M,N] row-major.
// Tile: BM=128, BN=64, BK=16; 256 threads; 8x4 microtile.
// blockIdx.z = batch; per-operand batch strides.
// ---------------------------------------------------------------------------
#define GBM 128
#define GBN 64
#define GBK 16

__global__ __launch_bounds__(256) void gemm_abt(
    const float* __restrict__ A, const float* __restrict__ B, float* __restrict__ C,
    int M, int N, int K,
    long sA, long sB, long sC,
    const float* __restrict__ bias,
    const float* __restrict__ resid, long sR)
{
    const int bb = blockIdx.z;
    A += (size_t)bb * sA;
    B += (size_t)bb * sB;
    C += (size_t)bb * sC;
    const float* rp = resid ? (resid + (size_t)bb * sR) : nullptr;

    const int m0 = blockIdx.y * GBM;
    const int n0 = blockIdx.x * GBN;

    __shared__ float As[GBM][GBK + 1];
    __shared__ float Bs[GBN][GBK + 1];

    const int tid = threadIdx.x;
    const int tx = tid & 15;   // n direction (4 cols)
    const int ty = tid >> 4;   // m direction (8 rows)

    float acc[8][4];
    #pragma unroll
    for (int i = 0; i < 8; i++)
        #pragma unroll
        for (int j = 0; j < 4; j++) acc[i][j] = 0.f;

    for (int k0 = 0; k0 < K; k0 += GBK) {
        // A tile: 128x16 = 512 float4, 2 per thread
        #pragma unroll
        for (int u = 0; u < 2; u++) {
            int f = tid + u * 256;
            int r = f >> 2, kq = (f & 3) << 2;
            float4 v = *(const float4*)(A + (size_t)(m0 + r) * K + k0 + kq);
            As[r][kq + 0] = v.x; As[r][kq + 1] = v.y;
            As[r][kq + 2] = v.z; As[r][kq + 3] = v.w;
        }
        // B tile: 64x16 = 256 float4, 1 per thread
        {
            int r = tid >> 2, kq = (tid & 3) << 2;
            float4 v = *(const float4*)(B + (size_t)(n0 + r) * K + k0 + kq);
            Bs[r][kq + 0] = v.x; Bs[r][kq + 1] = v.y;
            Bs[r][kq + 2] = v.z; Bs[r][kq + 3] = v.w;
        }
        __syncthreads();

        #pragma unroll
        for (int kk = 0; kk < GBK; kk++) {
            float a[8], bv[4];
            #pragma unroll
            for (int i = 0; i < 8; i++) a[i] = As[ty * 8 + i][kk];
            #pragma unroll
            for (int j = 0; j < 4; j++) bv[j] = Bs[tx * 4 + j][kk];
            #pragma unroll
            for (int i = 0; i < 8; i++)
                #pragma unroll
                for (int j = 0; j < 4; j++)
                    acc[i][j] += a[i] * bv[j];
        }
        __syncthreads();
    }

    // epilogue: float4 stores
    #pragma unroll
    for (int i = 0; i < 8; i++) {
        int m = m0 + ty * 8 + i;
        float bvv = bias ? bias[m] : 0.f;
        int n = n0 + tx * 4;
        float4 v;
        v.x = acc[i][0] + bvv; v.y = acc[i][1] + bvv;
        v.z = acc[i][2] + bvv; v.w = acc[i][3] + bvv;
        if (rp) {
            const float4 r4 = *(const float4*)(rp + (size_t)m * N + n);
            v.x += r4.x; v.y += r4.y; v.z += r4.z; v.w += r4.w;
        }
        *(float4*)(C + (size_t)m * N + n) = v;
    }
}

// ---------------------------------------------------------------------------
// Flash attention (fp32). One query per thread, 128 queries per block.
// grid: (S/128, NH, B); 128 threads.
// qkv layout: [B][3C][S]; Q channel (n*HD+d) row, S-contiguous.
// Output hf: [B][S][C], hf[b][s][n*HD+d].
// ---------------------------------------------------------------------------
#define ATK 64          // key tile
#define HDP 68          // padded head dim in smem (bank-friendly, 16B-aligned)

__global__ __launch_bounds__(128) void attn_kernel(
    const float* __restrict__ qkv, float* __restrict__ hf)
{
    const int b = blockIdx.z;
    const int n = blockIdx.y;
    const int s = blockIdx.x * 128 + threadIdx.x;

    const float* Qp = qkv + ((size_t)b * THREE_C + (size_t)n * HD) * SSP;
    const float* Kp = Qp + (size_t)CCH * SSP;
    const float* Vp = Qp + (size_t)2 * CCH * SSP;

    float q[HD];
    const float sc = 0.125f;   // hd^-0.5 = 1/8
    #pragma unroll
    for (int d = 0; d < HD; d++) q[d] = Qp[(size_t)d * SSP + s] * sc;

    __shared__ float Ks[ATK][HDP];
    __shared__ float Vs[ATK][HDP];

    float acc[HD];
    #pragma unroll
    for (int d = 0; d < HD; d++) acc[d] = 0.f;
    float m = -INFINITY, l = 0.f;

    for (int kt = 0; kt < SSP; kt += ATK) {
        __syncthreads();
        // cooperative load K/V tiles: flat over (d, j), j fast (coalesced gmem)
        #pragma unroll
        for (int u = 0; u < (ATK * HD) / 128; u++) {
            int i = u * 128 + threadIdx.x;
            int d = i >> 6;          // i / ATK  (ATK==64)
            int j = i & 63;          // i % ATK
            Ks[j][d] = Kp[(size_t)d * SSP + kt + j];
            Vs[j][d] = Vp[(size_t)d * SSP + kt + j];
        }
        __syncthreads();

        for (int j = 0; j < ATK; j++) {
            float sj = 0.f;
            #pragma unroll
            for (int d4 = 0; d4 < HD / 4; d4++) {
                float4 kk = *(const float4*)&Ks[j][d4 * 4];
                sj += q[d4 * 4 + 0] * kk.x + q[d4 * 4 + 1] * kk.y
                    + q[d4 * 4 + 2] * kk.z + q[d4 * 4 + 3] * kk.w;
            }
            if (sj > m) {            // lazy rescale (rare after warm-up)
                float f = __expf(m - sj);   // exp(-inf)=0 on first hit
                l *= f;
                #pragma unroll
                for (int d = 0; d < HD; d++) acc[d] *= f;
                m = sj;
            }
            float e = __expf(sj - m);
            l += e;
            #pragma unroll
            for (int d4 = 0; d4 < HD / 4; d4++) {
                float4 vv = *(const float4*)&Vs[j][d4 * 4];
                acc[d4 * 4 + 0] += e * vv.x;
                acc[d4 * 4 + 1] += e * vv.y;
                acc[d4 * 4 + 2] += e * vv.z;
                acc[d4 * 4 + 3] += e * vv.w;
            }
        }
    }

    const float linv = 1.f / l;
    float* op = hf + ((size_t)b * SSP + s) * CCH + (size_t)n * HD;
    #pragma unroll
    for (int d = 0; d < HD; d++) op[d] = acc[d] * linv;
}

// ---------------------------------------------------------------------------
// INL elementwise update: hf += DT * tanh(y + inl_b)
// ---------------------------------------------------------------------------
__global__ __launch_bounds__(256) void inl_update_kernel(
    float* __restrict__ hf, const float* __restrict__ y,
    const float* __restrict__ ib)
{
    size_t i = (size_t)blockIdx.x * 256 + threadIdx.x;
    int c = (int)(i & (CCH - 1));
    hf[i] += DT_INL * tanhf(y[i] + ib[c]);
}

// ---------------------------------------------------------------------------
// Launch
// Inputs: 0:x 1:gn_scale 2:gn_bias 3:qkv_w 4:qkv_b 5:proj_w 6:proj_b 7:inl_w 8:inl_b
// ---------------------------------------------------------------------------
extern "C" void kernel_launch(void* const* d_in, const int* in_sizes, int n_in,
                              void* d_out, int out_size)
{
    const float* x        = (const float*)d_in[0];
    const float* gn_scale = (const float*)d_in[1];
    const float* gn_bias  = (const float*)d_in[2];
    const float* qkv_w    = (const float*)d_in[3];
    const float* qkv_b    = (const float*)d_in[4];
    const float* proj_w   = (const float*)d_in[5];
    const float* proj_b   = (const float*)d_in[6];
    const float* inl_w    = (const float*)d_in[7];
    const float* inl_b    = (const float*)d_in[8];
    float* out = (float*)d_out;

    float *ht, *qkvbuf, *hf, *y;
    cudaGetSymbolAddress((void**)&ht,     g_ht);
    cudaGetSymbolAddress((void**)&qkvbuf, g_qkv);
    cudaGetSymbolAddress((void**)&hf,     g_hf);
    cudaGetSymbolAddress((void**)&y,      g_y);

    // 1) GroupNorm -> ht [B,S,C]
    gn_kernel<<<BATCH * NG, 256>>>(x, gn_scale, gn_bias, ht);

    // 2) QKV: per b, [1536,512] @ ht[b]^T -> qkv [B][3C][S]
    gemm_abt<<<dim3(SSP / GBN, THREE_C / GBM, BATCH), 256>>>(
        qkv_w, ht, qkvbuf,
        THREE_C, SSP, CCH,
        0L, (long)SSP * CCH, (long)THREE_C * SSP,
        qkv_b, nullptr, 0L);

    // 3) Attention -> hf [B,S,C]
    attn_kernel<<<dim3(SSP / 128, NH, BATCH), 128>>>(qkvbuf, hf);

    // 4) INL refinement: 3x (y = hf @ inl_w^T ; hf += dt*tanh(y + b))
    for (int it = 0; it < 3; it++) {
        gemm_abt<<<dim3(CCH / GBN, SSP / GBM, BATCH), 256>>>(
            hf, inl_w, y,
            SSP, CCH, CCH,
            (long)SSP * CCH, 0L, (long)SSP * CCH,
            nullptr, nullptr, 0L);
        inl_update_kernel<<<(BATCH * SSP * CCH) / 256, 256>>>(hf, y, inl_b);
    }

    // 5) Proj + bias + residual -> out [B,C,H,W]
    gemm_abt<<<dim3(SSP / GBN, CCH / GBM, BATCH), 256>>>(
        proj_w, hf, out,
        CCH, SSP, CCH,
        0L, (long)SSP * CCH, (long)CCH * SSP,
        proj_b, x, (long)CCH * SSP);
}

// round 5
// speedup vs baseline: 1.3542x; 1.3542x over previous
#include <cuda_runtime.h>
#include <cuda_bf16.h>
#include <math.h>
#include <stdint.h>

// Problem constants
#define BATCH 8
#define CCH   512
#define SSP   1024
#define NG    8
#define CPG   64
#define NH    8
#define HD    64
#define THREE_C 1536
#define EPS_GN 1e-5f
#define DT_INL 0.1f

#define KTRIP  1536        // 3 * CCH (split-precision concatenated K)
#define MT 128
#define NT 128
#define BKK 32
#define NIT (KTRIP / BKK)  // 48

// ---------------------------------------------------------------------------
// Scratch (device globals)
// ---------------------------------------------------------------------------
__device__ __align__(1024) float g_ht [BATCH * SSP * CCH];
__device__ __align__(1024) float g_qkv[BATCH * THREE_C * SSP];
__device__ __align__(1024) float g_hf [BATCH * SSP * CCH];
__device__ __align__(1024) __nv_bfloat16 g_ht2 [BATCH * SSP * KTRIP];
__device__ __align__(1024) __nv_bfloat16 g_hf2 [BATCH * SSP * KTRIP];
__device__ __align__(1024) __nv_bfloat16 g_wq2 [THREE_C * KTRIP];
__device__ __align__(1024) __nv_bfloat16 g_wi2 [CCH * KTRIP];
__device__ __align__(1024) __nv_bfloat16 g_wp2 [CCH * KTRIP];

// ---------------------------------------------------------------------------
// PTX helpers (baseline-PTX safe: mma.sync / ldmatrix / cp.async)
// ---------------------------------------------------------------------------
__device__ __forceinline__ uint32_t smem_u32(const void* p) {
    uint32_t a;
    asm("{ .reg .u64 t; cvta.to.shared.u64 t, %1; cvt.u32.u64 %0, t; }" : "=r"(a) : "l"(p));
    return a;
}
__device__ __forceinline__ void cpasync16(uint32_t s, const void* g) {
    asm volatile("cp.async.cg.shared.global [%0], [%1], 16;" :: "r"(s), "l"(g));
}
#define CP_COMMIT() asm volatile("cp.async.commit_group;" ::: "memory")
#define CP_WAIT0()  asm volatile("cp.async.wait_group 0;" ::: "memory")

#define LDSM_X4(r0, r1, r2, r3, a) \
    asm volatile("ldmatrix.sync.aligned.m8n8.x4.shared.b16 {%0,%1,%2,%3}, [%4];" \
        : "=r"(r0), "=r"(r1), "=r"(r2), "=r"(r3) : "r"(a))

__device__ __forceinline__ void mma16816(float* d,
    uint32_t a0, uint32_t a1, uint32_t a2, uint32_t a3,
    uint32_t b0, uint32_t b1)
{
    asm volatile(
        "mma.sync.aligned.m16n8k16.row.col.f32.bf16.bf16.f32 "
        "{%0,%1,%2,%3}, {%4,%5,%6,%7}, {%8,%9}, {%0,%1,%2,%3};"
        : "+f"(d[0]), "+f"(d[1]), "+f"(d[2]), "+f"(d[3])
        : "r"(a0), "r"(a1), "r"(a2), "r"(a3), "r"(b0), "r"(b1));
}

// ---------------------------------------------------------------------------
// GroupNorm + transpose to [B, S, C]
// ---------------------------------------------------------------------------
__global__ __launch_bounds__(256) void gn_kernel(
    const float* __restrict__ x, const float* __restrict__ scale,
    const float* __restrict__ bias, float* __restrict__ ht)
{
    const int b = blockIdx.x / NG;
    const int g = blockIdx.x % NG;
    const float* xp = x + ((size_t)b * CCH + (size_t)g * CPG) * SSP;
    const int NEL = CPG * SSP;

    float s = 0.f, s2 = 0.f;
    for (int i = threadIdx.x; i < NEL; i += 256) {
        float v = xp[i];
        s += v; s2 += v * v;
    }
    #pragma unroll
    for (int o = 16; o > 0; o >>= 1) {
        s  += __shfl_down_sync(0xffffffffu, s,  o);
        s2 += __shfl_down_sync(0xffffffffu, s2, o);
    }
    __shared__ float ws[8], ws2[8];
    __shared__ float sh_mean, sh_inv;
    const int wid = threadIdx.x >> 5, lane = threadIdx.x & 31;
    if (lane == 0) { ws[wid] = s; ws2[wid] = s2; }
    __syncthreads();
    if (threadIdx.x == 0) {
        float S = 0.f, S2 = 0.f;
        #pragma unroll
        for (int w = 0; w < 8; w++) { S += ws[w]; S2 += ws2[w]; }
        float mean = S / (float)NEL;
        float var  = S2 / (float)NEL - mean * mean;
        sh_mean = mean;
        sh_inv  = rsqrtf(var + EPS_GN);
    }
    __syncthreads();
    const float mean = sh_mean, inv = sh_inv;
    for (int i = threadIdx.x; i < NEL; i += 256) {
        int c    = g * CPG + (i / SSP);
        int spos = i % SSP;
        float v = (xp[i] - mean) * inv * scale[c] + bias[c];
        ht[((size_t)b * SSP + spos) * CCH + c] = v;
    }
}

// ---------------------------------------------------------------------------
// Split-precision conversion: fp32 [rows,512] -> bf16 [rows,1536]
// pattern A (pb=0): [hi | hi | lo], pattern B (pb=1): [hi | lo | hi]
// ---------------------------------------------------------------------------
__global__ __launch_bounds__(256) void conv_split(
    const float* __restrict__ in, __nv_bfloat16* __restrict__ out, int pb)
{
    int i = blockIdx.x * 256 + threadIdx.x;
    int r = i >> 7;
    int c = (i & 127) << 2;
    float4 v = ((const float4*)in)[i];
    __nv_bfloat16 hx = __float2bfloat16(v.x), hy = __float2bfloat16(v.y);
    __nv_bfloat16 hz = __float2bfloat16(v.z), hw = __float2bfloat16(v.w);
    __nv_bfloat16 lx = __float2bfloat16(v.x - __bfloat162float(hx));
    __nv_bfloat16 ly = __float2bfloat16(v.y - __bfloat162float(hy));
    __nv_bfloat16 lz = __float2bfloat16(v.z - __bfloat162float(hz));
    __nv_bfloat16 lw = __float2bfloat16(v.w - __bfloat162float(hw));
    __nv_bfloat162 h0; h0.x = hx; h0.y = hy;
    __nv_bfloat162 h1; h1.x = hz; h1.y = hw;
    __nv_bfloat162 l0; l0.x = lx; l0.y = ly;
    __nv_bfloat162 l1; l1.x = lz; l1.y = lw;
    __nv_bfloat162* o = (__nv_bfloat162*)(out + (size_t)r * KTRIP + c);
    o[0] = h0; o[1] = h1;
    __nv_bfloat162* o1 = o + (CCH >> 1);
    __nv_bfloat162* o2 = o + (CCH);
    if (pb) { o1[0] = l0; o1[1] = l1; o2[0] = h0; o2[1] = h1; }
    else    { o1[0] = h0; o1[1] = h1; o2[0] = l0; o2[1] = l1; }
}

// ---------------------------------------------------------------------------
// HMMA bf16 GEMM: C[m][n] = sum_k A2[m][k]*B2[n][k]   (K' = 1536)
// CTA 128x128, BK=32, 256 threads, warp tile 64x32, cp.async double buffer.
// epilogue: v = acc + biasM[m] + biasN[n]; tanh_mode ? resid + dt*tanh(v)
//                                                    : v + (resid ? resid : 0)
// ---------------------------------------------------------------------------
#define APITCH 40          // bf16 elements per smem row (32 data + 8 pad = 80B)

__global__ __launch_bounds__(256) void mm_mma(
    const __nv_bfloat16* __restrict__ A, long sA,
    const __nv_bfloat16* __restrict__ B, long sB,
    float* __restrict__ C, int ldc, long sC,
    const float* __restrict__ biasM,
    const float* __restrict__ biasN,
    const float* __restrict__ resid, int ldr, long sR,
    int tanh_mode)
{
    __shared__ __align__(16) __nv_bfloat16 As[2][MT][APITCH];
    __shared__ __align__(16) __nv_bfloat16 Bs[2][NT][APITCH];

    const int tid  = threadIdx.x;
    const int wid  = tid >> 5;
    const int lane = tid & 31;
    const int wm   = wid & 1;       // 0/1 -> m offset 0/64
    const int wn   = wid >> 1;      // 0..3 -> n offset wn*32

    const int bb = blockIdx.z;
    A += (size_t)bb * sA;
    B += (size_t)bb * sB;
    C += (size_t)bb * sC;
    const float* rp = resid ? (resid + (size_t)bb * sR) : nullptr;
    const int m0 = blockIdx.y * MT;
    const int n0 = blockIdx.x * NT;

    const uint32_t sa0 = smem_u32(&As[0][0][0]);
    const uint32_t sb0 = smem_u32(&Bs[0][0][0]);
    const uint32_t STG = MT * APITCH * 2;      // bytes per stage (10240)

    float acc[4][4][4];
    #pragma unroll
    for (int mi = 0; mi < 4; mi++)
        #pragma unroll
        for (int ni = 0; ni < 4; ni++)
            #pragma unroll
            for (int r = 0; r < 4; r++) acc[mi][ni][r] = 0.f;

    // gmem->smem tile loader (A and B tiles, 512 16B chunks each)
    const int lr = tid >> 2;           // 0..63 base row
    const int lc = tid & 3;            // 16B chunk within row
    #define LOAD_TILES(k0, st) do {                                              \
        uint32_t _sa = sa0 + (st) * STG;                                         \
        uint32_t _sb = sb0 + (st) * STG;                                         \
        _Pragma("unroll")                                                        \
        for (int u = 0; u < 2; u++) {                                            \
            int r = lr + u * 64;                                                 \
            cpasync16(_sa + r * 80 + lc * 16,                                    \
                      A + (size_t)(m0 + r) * KTRIP + (k0) + lc * 8);             \
            cpasync16(_sb + r * 80 + lc * 16,                                    \
                      B + (size_t)(n0 + r) * KTRIP + (k0) + lc * 8);             \
        }                                                                        \
    } while (0)

    LOAD_TILES(0, 0);
    CP_COMMIT();

    // ldmatrix base addresses (lane-dependent parts)
    const uint32_t a_lbase = (wm * 64 + (lane & 15)) * 80 + ((lane >> 4) << 4);
    const uint32_t b_lbase = (wn * 32 + (lane & 7) + ((lane >> 4) & 1) * 8) * 80
                           + (((lane >> 3) & 1) << 4);

    for (int it = 0; it < NIT; it++) {
        CP_WAIT0();
        __syncthreads();
        if (it + 1 < NIT) {
            LOAD_TILES((it + 1) * BKK, (it + 1) & 1);
            CP_COMMIT();
        }
        const int st = it & 1;
        const uint32_t sa = sa0 + st * STG;
        const uint32_t sb = sb0 + st * STG;

        #pragma unroll
        for (int kp = 0; kp < 2; kp++) {
            uint32_t af[4][4];
            #pragma unroll
            for (int mi = 0; mi < 4; mi++)
                LDSM_X4(af[mi][0], af[mi][1], af[mi][2], af[mi][3],
                        sa + a_lbase + mi * (16 * 80) + kp * 32);
            uint32_t bf[2][4];
            #pragma unroll
            for (int pi = 0; pi < 2; pi++)
                LDSM_X4(bf[pi][0], bf[pi][1], bf[pi][2], bf[pi][3],
                        sb + b_lbase + pi * (16 * 80) + kp * 32);
            #pragma unroll
            for (int mi = 0; mi < 4; mi++)
                #pragma unroll
                for (int ni = 0; ni < 4; ni++)
                    mma16816(acc[mi][ni],
                             af[mi][0], af[mi][1], af[mi][2], af[mi][3],
                             bf[ni >> 1][(ni & 1) * 2],
                             bf[ni >> 1][(ni & 1) * 2 + 1]);
        }
        __syncthreads();
    }

    // Epilogue
    const int mb = m0 + wm * 64;
    const int nb = n0 + wn * 32;
    const int rbase = lane >> 2;
    const int cbase = (lane & 3) * 2;
    #pragma unroll
    for (int mi = 0; mi < 4; mi++) {
        #pragma unroll
        for (int h = 0; h < 2; h++) {
            const int m = mb + mi * 16 + rbase + h * 8;
            const float bm = biasM ? biasM[m] : 0.f;
            #pragma unroll
            for (int ni = 0; ni < 4; ni++) {
                const int n = nb + ni * 8 + cbase;
                float v0 = acc[mi][ni][h * 2 + 0] + bm;
                float v1 = acc[mi][ni][h * 2 + 1] + bm;
                if (biasN) { v0 += biasN[n]; v1 += biasN[n + 1]; }
                float2 o;
                if (tanh_mode) {
                    const float2 r2 = *(const float2*)(rp + (size_t)m * ldr + n);
                    o.x = r2.x + DT_INL * tanhf(v0);
                    o.y = r2.y + DT_INL * tanhf(v1);
                } else {
                    o.x = v0; o.y = v1;
                    if (rp) {
                        const float2 r2 = *(const float2*)(rp + (size_t)m * ldr + n);
                        o.x += r2.x; o.y += r2.y;
                    }
                }
                *(float2*)(C + (size_t)m * ldc + n) = o;
            }
        }
    }
}

// ---------------------------------------------------------------------------
// Flash attention (fp32), unchanged
// ---------------------------------------------------------------------------
#define ATK 64
#define HDP 68

__global__ __launch_bounds__(128) void attn_kernel(
    const float* __restrict__ qkv, float* __restrict__ hf)
{
    const int b = blockIdx.z;
    const int n = blockIdx.y;
    const int s = blockIdx.x * 128 + threadIdx.x;

    const float* Qp = qkv + ((size_t)b * THREE_C + (size_t)n * HD) * SSP;
    const float* Kp = Qp + (size_t)CCH * SSP;
    const float* Vp = Qp + (size_t)2 * CCH * SSP;

    float q[HD];
    const float sc = 0.125f;
    #pragma unroll
    for (int d = 0; d < HD; d++) q[d] = Qp[(size_t)d * SSP + s] * sc;

    __shared__ float Ks[ATK][HDP];
    __shared__ float Vs[ATK][HDP];

    float acc[HD];
    #pragma unroll
    for (int d = 0; d < HD; d++) acc[d] = 0.f;
    float m = -INFINITY, l = 0.f;

    for (int kt = 0; kt < SSP; kt += ATK) {
        __syncthreads();
        #pragma unroll
        for (int u = 0; u < (ATK * HD) / 128; u++) {
            int i = u * 128 + threadIdx.x;
            int d = i >> 6;
            int j = i & 63;
            Ks[j][d] = Kp[(size_t)d * SSP + kt + j];
            Vs[j][d] = Vp[(size_t)d * SSP + kt + j];
        }
        __syncthreads();

        for (int j = 0; j < ATK; j++) {
            float sj = 0.f;
            #pragma unroll
            for (int d4 = 0; d4 < HD / 4; d4++) {
                float4 kk = *(const float4*)&Ks[j][d4 * 4];
                sj += q[d4 * 4 + 0] * kk.x + q[d4 * 4 + 1] * kk.y
                    + q[d4 * 4 + 2] * kk.z + q[d4 * 4 + 3] * kk.w;
            }
            if (sj > m) {
                float f = __expf(m - sj);
                l *= f;
                #pragma unroll
                for (int d = 0; d < HD; d++) acc[d] *= f;
                m = sj;
            }
            float e = __expf(sj - m);
            l += e;
            #pragma unroll
            for (int d4 = 0; d4 < HD / 4; d4++) {
                float4 vv = *(const float4*)&Vs[j][d4 * 4];
                acc[d4 * 4 + 0] += e * vv.x;
                acc[d4 * 4 + 1] += e * vv.y;
                acc[d4 * 4 + 2] += e * vv.z;
                acc[d4 * 4 + 3] += e * vv.w;
            }
        }
    }

    const float linv = 1.f / l;
    float* op = hf + ((size_t)b * SSP + s) * CCH + (size_t)n * HD;
    #pragma unroll
    for (int d = 0; d < HD; d++) op[d] = acc[d] * linv;
}

// ---------------------------------------------------------------------------
// Launch
// ---------------------------------------------------------------------------
extern "C" void kernel_launch(void* const* d_in, const int* in_sizes, int n_in,
                              void* d_out, int out_size)
{
    const float* x        = (const float*)d_in[0];
    const float* gn_scale = (const float*)d_in[1];
    const float* gn_bias  = (const float*)d_in[2];
    const float* qkv_w    = (const float*)d_in[3];
    const float* qkv_b    = (const float*)d_in[4];
    const float* proj_w   = (const float*)d_in[5];
    const float* proj_b   = (const float*)d_in[6];
    const float* inl_w    = (const float*)d_in[7];
    const float* inl_b    = (const float*)d_in[8];
    float* out = (float*)d_out;

    float *ht, *qkvbuf, *hf;
    __nv_bfloat16 *ht2, *hf2, *wq2, *wi2, *wp2;
    cudaGetSymbolAddress((void**)&ht,     g_ht);
    cudaGetSymbolAddress((void**)&qkvbuf, g_qkv);
    cudaGetSymbolAddress((void**)&hf,     g_hf);
    cudaGetSymbolAddress((void**)&ht2,    g_ht2);
    cudaGetSymbolAddress((void**)&hf2,    g_hf2);
    cudaGetSymbolAddress((void**)&wq2,    g_wq2);
    cudaGetSymbolAddress((void**)&wi2,    g_wi2);
    cudaGetSymbolAddress((void**)&wp2,    g_wp2);

    // 1) GroupNorm -> ht [B,S,C]
    gn_kernel<<<BATCH * NG, 256>>>(x, gn_scale, gn_bias, ht);

    // 2) conversions
    conv_split<<<(BATCH * SSP * CCH / 4) / 256, 256>>>(ht, ht2, 1);      // B-pattern
    conv_split<<<(THREE_C * CCH / 4) / 256, 256>>>(qkv_w, wq2, 0);       // A-pattern
    conv_split<<<(CCH * CCH / 4) / 256, 256>>>(inl_w, wi2, 1);           // B-pattern
    conv_split<<<(CCH * CCH / 4) / 256, 256>>>(proj_w, wp2, 0);          // A-pattern

    // 3) QKV: C[3C][S] = qkv_w @ ht^T
    mm_mma<<<dim3(SSP / NT, THREE_C / MT, BATCH), 256>>>(
        wq2, 0L, ht2, (long)SSP * KTRIP,
        qkvbuf, SSP, (long)THREE_C * SSP,
        qkv_b, nullptr, nullptr, 0, 0L, 0);

    // 4) Attention -> hf [B,S,C]
    attn_kernel<<<dim3(SSP / 128, NH, BATCH), 128>>>(qkvbuf, hf);

    // 5) INL x3: hf <- hf + dt*tanh(hf @ inl_w^T + b)  (fused, in place)
    for (int it = 0; it < 3; it++) {
        conv_split<<<(BATCH * SSP * CCH / 4) / 256, 256>>>(hf, hf2, 0);  // A-pattern
        mm_mma<<<dim3(CCH / NT, SSP / MT, BATCH), 256>>>(
            hf2, (long)SSP * KTRIP, wi2, 0L,
            hf, CCH, (long)SSP * CCH,
            nullptr, inl_b, hf, CCH, (long)SSP * CCH, 1);
    }

    // 6) Proj + bias + residual -> out [B,C,S]
    conv_split<<<(BATCH * SSP * CCH / 4) / 256, 256>>>(hf, hf2, 1);      // B-pattern
    mm_mma<<<dim3(SSP / NT, CCH / MT, BATCH), 256>>>(
        wp2, 0L, hf2, (long)SSP * KTRIP,
        out, SSP, (long)CCH * SSP,
        proj_b, nullptr, x, SSP, (long)CCH * SSP, 0);
}

// round 6
// speedup vs baseline: 1.6324x; 1.2054x over previous
#include <cuda_runtime.h>
#include <cuda_bf16.h>
#include <math.h>
#include <stdint.h>

// Problem constants
#define BATCH 8
#define CCH   512
#define SSP   1024
#define NG    8
#define CPG   64
#define NH    8
#define HD    64
#define THREE_C 1536
#define EPS_GN 1e-5f
#define DT_INL 0.1f

#define KTRIP  1536        // 3 * CCH (split-precision concatenated K)
#define NBH    64          // BATCH * NH

// ---------------------------------------------------------------------------
// Scratch (device globals)
// ---------------------------------------------------------------------------
__device__ __align__(1024) float g_ht [BATCH * SSP * CCH];
__device__ __align__(1024) float g_qkv[BATCH * SSP * THREE_C];     // [B][S][3C]
__device__ __align__(1024) float g_hf [BATCH * SSP * CCH];
__device__ __align__(1024) float g_S  [NBH * SSP * SSP];           // logits
__device__ __align__(1024) __nv_bfloat16 g_P  [NBH * SSP * 2048];  // p_hi|p_lo
__device__ __align__(1024) __nv_bfloat16 g_qh [NBH * SSP * 192];   // Q split (A)
__device__ __align__(1024) __nv_bfloat16 g_kh [NBH * SSP * 192];   // K split (B)
__device__ __align__(1024) __nv_bfloat16 g_vt [NBH * HD * 2048];   // V^T hi|lo
__device__ __align__(1024) __nv_bfloat16 g_ht2 [BATCH * SSP * KTRIP];
__device__ __align__(1024) __nv_bfloat16 g_hf2 [BATCH * SSP * KTRIP];
__device__ __align__(1024) __nv_bfloat16 g_wq2 [THREE_C * KTRIP];
__device__ __align__(1024) __nv_bfloat16 g_wi2 [CCH * KTRIP];
__device__ __align__(1024) __nv_bfloat16 g_wp2 [CCH * KTRIP];

// ---------------------------------------------------------------------------
// PTX helpers
// ---------------------------------------------------------------------------
__device__ __forceinline__ uint32_t smem_u32(const void* p) {
    uint32_t a;
    asm("{ .reg .u64 t; cvta.to.shared.u64 t, %1; cvt.u32.u64 %0, t; }" : "=r"(a) : "l"(p));
    return a;
}
__device__ __forceinline__ void cpasync16(uint32_t s, const void* g) {
    asm volatile("cp.async.cg.shared.global [%0], [%1], 16;" :: "r"(s), "l"(g));
}
#define CP_COMMIT() asm volatile("cp.async.commit_group;" ::: "memory")
#define CP_WAIT0()  asm volatile("cp.async.wait_group 0;" ::: "memory")

#define LDSM_X4(r0, r1, r2, r3, a) \
    asm volatile("ldmatrix.sync.aligned.m8n8.x4.shared.b16 {%0,%1,%2,%3}, [%4];" \
        : "=r"(r0), "=r"(r1), "=r"(r2), "=r"(r3) : "r"(a))

__device__ __forceinline__ void mma16816(float* d,
    uint32_t a0, uint32_t a1, uint32_t a2, uint32_t a3,
    uint32_t b0, uint32_t b1)
{
    asm volatile(
        "mma.sync.aligned.m16n8k16.row.col.f32.bf16.bf16.f32 "
        "{%0,%1,%2,%3}, {%4,%5,%6,%7}, {%8,%9}, {%0,%1,%2,%3};"
        : "+f"(d[0]), "+f"(d[1]), "+f"(d[2]), "+f"(d[3])
        : "r"(a0), "r"(a1), "r"(a2), "r"(a3), "r"(b0), "r"(b1));
}

__device__ __forceinline__ void split2(float x, float y,
    __nv_bfloat162& h2, __nv_bfloat162& l2)
{
    h2.x = __float2bfloat16(x); h2.y = __float2bfloat16(y);
    l2.x = __float2bfloat16(x - __bfloat162float(h2.x));
    l2.y = __float2bfloat16(y - __bfloat162float(h2.y));
}

// ---------------------------------------------------------------------------
// GroupNorm + transpose to [B, S, C]
// ---------------------------------------------------------------------------
__global__ __launch_bounds__(256) void gn_kernel(
    const float* __restrict__ x, const float* __restrict__ scale,
    const float* __restrict__ bias, float* __restrict__ ht)
{
    const int b = blockIdx.x / NG;
    const int g = blockIdx.x % NG;
    const float* xp = x + ((size_t)b * CCH + (size_t)g * CPG) * SSP;
    const int NEL = CPG * SSP;

    float s = 0.f, s2 = 0.f;
    for (int i = threadIdx.x; i < NEL; i += 256) {
        float v = xp[i];
        s += v; s2 += v * v;
    }
    #pragma unroll
    for (int o = 16; o > 0; o >>= 1) {
        s  += __shfl_down_sync(0xffffffffu, s,  o);
        s2 += __shfl_down_sync(0xffffffffu, s2, o);
    }
    __shared__ float ws[8], ws2[8];
    __shared__ float sh_mean, sh_inv;
    const int wid = threadIdx.x >> 5, lane = threadIdx.x & 31;
    if (lane == 0) { ws[wid] = s; ws2[wid] = s2; }
    __syncthreads();
    if (threadIdx.x == 0) {
        float S = 0.f, S2 = 0.f;
        #pragma unroll
        for (int w = 0; w < 8; w++) { S += ws[w]; S2 += ws2[w]; }
        float mean = S / (float)NEL;
        float var  = S2 / (float)NEL - mean * mean;
        sh_mean = mean;
        sh_inv  = rsqrtf(var + EPS_GN);
    }
    __syncthreads();
    const float mean = sh_mean, inv = sh_inv;
    for (int i = threadIdx.x; i < NEL; i += 256) {
        int c    = g * CPG + (i / SSP);
        int spos = i % SSP;
        float v = (xp[i] - mean) * inv * scale[c] + bias[c];
        ht[((size_t)b * SSP + spos) * CCH + c] = v;
    }
}

// ---------------------------------------------------------------------------
// Split-precision conversion: fp32 [rows,512] -> bf16 [rows,1536]
// pattern A (pb=0): [hi | hi | lo], pattern B (pb=1): [hi | lo | hi]
// ---------------------------------------------------------------------------
__global__ __launch_bounds__(256) void conv_split(
    const float* __restrict__ in, __nv_bfloat16* __restrict__ out, int pb)
{
    int i = blockIdx.x * 256 + threadIdx.x;
    int r = i >> 7;
    int c = (i & 127) << 2;
    float4 v = ((const float4*)in)[i];
    __nv_bfloat162 h0, h1, l0, l1;
    split2(v.x, v.y, h0, l0);
    split2(v.z, v.w, h1, l1);
    __nv_bfloat162* o = (__nv_bfloat162*)(out + (size_t)r * KTRIP + c);
    o[0] = h0; o[1] = h1;
    __nv_bfloat162* o1 = o + (CCH >> 1);
    __nv_bfloat162* o2 = o + (CCH);
    if (pb) { o1[0] = l0; o1[1] = l1; o2[0] = h0; o2[1] = h1; }
    else    { o1[0] = h0; o1[1] = h1; o2[0] = l0; o2[1] = l1; }
}

// ---------------------------------------------------------------------------
// Q/K per-head split conversion from qkv [B][S][3C]
// Q: scaled by 1/8, pattern A -> g_qh [z][s][192]
// K: pattern B -> g_kh [z][s][192]
// grid (64 s-tiles, 1, 64 z), 256 thr: 16 rows x 16 f4-chunks
// ---------------------------------------------------------------------------
__global__ __launch_bounds__(256) void qk_conv(
    const float* __restrict__ qkv, __nv_bfloat16* __restrict__ Qh,
    __nv_bfloat16* __restrict__ Kh)
{
    const int z = blockIdx.z;
    const int b = z >> 3, h = z & 7;
    const int s = blockIdx.x * 16 + (threadIdx.x >> 4);
    const int c4 = threadIdx.x & 15;

    const float* base = qkv + ((size_t)b * SSP + s) * THREE_C + h * HD + c4 * 4;
    // Q
    {
        float4 v = *(const float4*)base;
        v.x *= 0.125f; v.y *= 0.125f; v.z *= 0.125f; v.w *= 0.125f;
        __nv_bfloat162 h0, h1, l0, l1;
        split2(v.x, v.y, h0, l0);
        split2(v.z, v.w, h1, l1);
        __nv_bfloat162* o = (__nv_bfloat162*)(Qh + ((size_t)z * SSP + s) * 192 + c4 * 4);
        o[0] = h0; o[1] = h1;               // hi
        o[32] = h0; o[33] = h1;             // +64: hi
        o[64] = l0; o[65] = l1;             // +128: lo
    }
    // K
    {
        float4 v = *(const float4*)(base + CCH);
        __nv_bfloat162 h0, h1, l0, l1;
        split2(v.x, v.y, h0, l0);
        split2(v.z, v.w, h1, l1);
        __nv_bfloat162* o = (__nv_bfloat162*)(Kh + ((size_t)z * SSP + s) * 192 + c4 * 4);
        o[0] = h0; o[1] = h1;               // hi
        o[32] = l0; o[33] = l1;             // +64: lo
        o[64] = h0; o[65] = h1;             // +128: hi
    }
}

// ---------------------------------------------------------------------------
// V transpose + split: qkv [B][S][3C] (V at +2C) -> Vt [z][d][ v_hi(1024) | v_lo(1024) ]
// grid (8 t-tiles, 1, 64 z), 256 thr
// ---------------------------------------------------------------------------
__global__ __launch_bounds__(256) void v_conv(
    const float* __restrict__ qkv, __nv_bfloat16* __restrict__ Vt)
{
    const int z = blockIdx.z;
    const int b = z >> 3, h = z & 7;
    const int tt = blockIdx.x * 128;
    __shared__ float ts[128][65];

    const float* src = qkv + ((size_t)b * SSP + tt) * THREE_C + 2 * CCH + h * HD;
    #pragma unroll
    for (int u = 0; u < 8; u++) {
        int i = u * 256 + threadIdx.x;
        int r = i >> 4, c4 = i & 15;
        float4 v = *(const float4*)(src + (size_t)r * THREE_C + c4 * 4);
        ts[r][c4 * 4 + 0] = v.x; ts[r][c4 * 4 + 1] = v.y;
        ts[r][c4 * 4 + 2] = v.z; ts[r][c4 * 4 + 3] = v.w;
    }
    __syncthreads();
    #pragma unroll
    for (int u = 0; u < 8; u++) {
        int i = u * 256 + threadIdx.x;
        int d = i >> 5, t4 = (i & 31) * 4;
        float v0 = ts[t4 + 0][d], v1 = ts[t4 + 1][d];
        float v2 = ts[t4 + 2][d], v3 = ts[t4 + 3][d];
        __nv_bfloat162 h0, h1, l0, l1;
        split2(v0, v1, h0, l0);
        split2(v2, v3, h1, l1);
        __nv_bfloat16* o = Vt + ((size_t)z * HD + d) * 2048 + tt + t4;
        *(__nv_bfloat162*)(o)          = h0;
        *(__nv_bfloat162*)(o + 2)      = h1;
        *(__nv_bfloat162*)(o + 1024)   = l0;
        *(__nv_bfloat162*)(o + 1026)   = l1;
    }
}

// ---------------------------------------------------------------------------
// Row softmax: Sbuf [row][1024] fp32 -> P [row][ p_hi(1024) | p_lo(1024) ]
// warp per row, 8 rows per block
// ---------------------------------------------------------------------------
__global__ __launch_bounds__(256) void softmax_k(
    const float* __restrict__ Sb, __nv_bfloat16* __restrict__ P)
{
    const int wid = threadIdx.x >> 5, lane = threadIdx.x & 31;
    const size_t row = (size_t)blockIdx.x * 8 + wid;
    const float* r = Sb + row * SSP;

    float v[32];
    #pragma unroll
    for (int u = 0; u < 8; u++) {
        float4 f = *(const float4*)(r + u * 128 + lane * 4);
        v[u * 4 + 0] = f.x; v[u * 4 + 1] = f.y; v[u * 4 + 2] = f.z; v[u * 4 + 3] = f.w;
    }
    float m = v[0];
    #pragma unroll
    for (int i = 1; i < 32; i++) m = fmaxf(m, v[i]);
    #pragma unroll
    for (int o = 16; o > 0; o >>= 1) m = fmaxf(m, __shfl_xor_sync(0xffffffffu, m, o));
    float l = 0.f;
    #pragma unroll
    for (int i = 0; i < 32; i++) { v[i] = __expf(v[i] - m); l += v[i]; }
    #pragma unroll
    for (int o = 16; o > 0; o >>= 1) l += __shfl_xor_sync(0xffffffffu, l, o);
    const float inv = 1.f / l;

    __nv_bfloat16* op = P + row * 2048;
    #pragma unroll
    for (int u = 0; u < 8; u++) {
        int c = u * 128 + lane * 4;
        float p0 = v[u*4+0] * inv, p1 = v[u*4+1] * inv;
        float p2 = v[u*4+2] * inv, p3 = v[u*4+3] * inv;
        __nv_bfloat162 h0, h1, l0, l1;
        split2(p0, p1, h0, l0);
        split2(p2, p3, h1, l1);
        *(__nv_bfloat162*)(op + c)          = h0;
        *(__nv_bfloat162*)(op + c + 2)      = h1;
        *(__nv_bfloat162*)(op + c + 1024)   = l0;
        *(__nv_bfloat162*)(op + c + 1026)   = l1;
    }
}

// ---------------------------------------------------------------------------
// Templated HMMA bf16 GEMM: C[m][n] = sum_k A[m][k]*B[n][k]
// MT_ x NT_ CTA tile, 8 warps in WM_ x (8/WM_) grid, BK=32, double-buffered.
// K mapped through 3 segments of segLen with additive offsets (for PV reuse).
// Epilogue: v = acc + biasM[m] + biasN[n]; tanh_mode ? resid + dt*tanh(v) : v + resid
//           optional split-out (pattern A) to sout.
// ---------------------------------------------------------------------------
template<int MT_, int NT_, int WM_>
__global__ __launch_bounds__(256) void mm_mma(
    const __nv_bfloat16* __restrict__ A, long lda, long sA,
    const __nv_bfloat16* __restrict__ B, long ldb, long sB,
    float* __restrict__ C, int ldc, int zdiv, long sC1, long sC2,
    const float* __restrict__ biasM, const float* __restrict__ biasN,
    const float* __restrict__ resid, int ldr, long sR1,
    int tanh_mode,
    __nv_bfloat16* __restrict__ sout, long sO1, long sO2,
    int kTot, long segLen, long aOff1, long aOff2, long bOff1, long bOff2)
{
    constexpr int WN_ = 8 / WM_;
    constexpr int WTM = MT_ / WM_;
    constexpr int WTN = NT_ / WN_;
    constexpr int MI  = WTM / 16;
    constexpr int NI  = WTN / 8;
    constexpr int NI2 = WTN / 16;

    __shared__ __align__(16) __nv_bfloat16 As[2][MT_][40];
    __shared__ __align__(16) __nv_bfloat16 Bs[2][NT_][40];

    const int tid  = threadIdx.x;
    const int wid  = tid >> 5;
    const int lane = tid & 31;
    const int wm   = wid % WM_;
    const int wn   = wid / WM_;

    const int bb = blockIdx.z;
    const int zo = bb / zdiv, zi = bb % zdiv;
    A += (size_t)bb * sA;
    B += (size_t)bb * sB;
    C += (size_t)zo * sC1 + (size_t)zi * sC2;
    const float* rp = resid ? (resid + (size_t)zo * sR1) : nullptr;
    __nv_bfloat16* so = sout ? (sout + (size_t)zo * sO1 + (size_t)zi * sO2) : nullptr;
    const int m0 = blockIdx.y * MT_;
    const int n0 = blockIdx.x * NT_;

    const uint32_t sa0 = smem_u32(&As[0][0][0]);
    const uint32_t sb0 = smem_u32(&Bs[0][0][0]);
    const uint32_t STGA = MT_ * 80;
    const uint32_t STGB = NT_ * 80;

    float acc[MI][NI][4];
    #pragma unroll
    for (int mi = 0; mi < MI; mi++)
        #pragma unroll
        for (int ni = 0; ni < NI; ni++)
            #pragma unroll
            for (int r = 0; r < 4; r++) acc[mi][ni][r] = 0.f;

    auto load_stage = [&](int it, int st) {
        long k0 = (long)it * 32;
        long ao = 0, bo = 0;
        if (k0 >= 2 * segLen)      { ao = aOff2; bo = bOff2; }
        else if (k0 >= segLen)     { ao = aOff1; bo = bOff1; }
        const __nv_bfloat16* Ak = A + k0 + ao;
        const __nv_bfloat16* Bk = B + k0 + bo;
        uint32_t _sa = sa0 + st * STGA;
        uint32_t _sb = sb0 + st * STGB;
        #pragma unroll
        for (int i = tid; i < MT_ * 4; i += 256) {
            int r = i >> 2, c = i & 3;
            cpasync16(_sa + r * 80 + c * 16, Ak + (size_t)(m0 + r) * lda + c * 8);
        }
        #pragma unroll
        for (int i = tid; i < NT_ * 4; i += 256) {
            int r = i >> 2, c = i & 3;
            cpasync16(_sb + r * 80 + c * 16, Bk + (size_t)(n0 + r) * ldb + c * 8);
        }
    };

    const int NIT = kTot / 32;
    load_stage(0, 0);
    CP_COMMIT();

    const uint32_t a_lbase = (wm * WTM + (lane & 15)) * 80 + ((lane >> 4) << 4);
    const uint32_t b_lbase = (wn * WTN + (lane & 7) + ((lane >> 4) & 1) * 8) * 80
                           + (((lane >> 3) & 1) << 4);

    for (int it = 0; it < NIT; it++) {
        CP_WAIT0();
        __syncthreads();
        if (it + 1 < NIT) {
            load_stage(it + 1, (it + 1) & 1);
            CP_COMMIT();
        }
        const int st = it & 1;
        const uint32_t sa = sa0 + st * STGA;
        const uint32_t sb = sb0 + st * STGB;

        #pragma unroll
        for (int kp = 0; kp < 2; kp++) {
            uint32_t af[MI][4];
            #pragma unroll
            for (int mi = 0; mi < MI; mi++)
                LDSM_X4(af[mi][0], af[mi][1], af[mi][2], af[mi][3],
                        sa + a_lbase + mi * (16 * 80) + kp * 32);
            uint32_t bf[NI2][4];
            #pragma unroll
            for (int pi = 0; pi < NI2; pi++)
                LDSM_X4(bf[pi][0], bf[pi][1], bf[pi][2], bf[pi][3],
                        sb + b_lbase + pi * (16 * 80) + kp * 32);
            #pragma unroll
            for (int mi = 0; mi < MI; mi++)
                #pragma unroll
                for (int ni = 0; ni < NI; ni++)
                    mma16816(acc[mi][ni],
                             af[mi][0], af[mi][1], af[mi][2], af[mi][3],
                             bf[ni >> 1][(ni & 1) * 2],
                             bf[ni >> 1][(ni & 1) * 2 + 1]);
        }
        __syncthreads();
    }

    // Epilogue
    const int mb = m0 + wm * WTM;
    const int nb = n0 + wn * WTN;
    const int rbase = lane >> 2;
    const int cbase = (lane & 3) * 2;
    #pragma unroll
    for (int mi = 0; mi < MI; mi++) {
        #pragma unroll
        for (int h = 0; h < 2; h++) {
            const int m = mb + mi * 16 + rbase + h * 8;
            const float bm = biasM ? biasM[m] : 0.f;
            #pragma unroll
            for (int ni = 0; ni < NI; ni++) {
                const int n = nb + ni * 8 + cbase;
                float v0 = acc[mi][ni][h * 2 + 0] + bm;
                float v1 = acc[mi][ni][h * 2 + 1] + bm;
                if (biasN) { v0 += biasN[n]; v1 += biasN[n + 1]; }
                float2 o;
                if (tanh_mode) {
                    const float2 r2 = *(const float2*)(rp + (size_t)m * ldr + n);
                    o.x = r2.x + DT_INL * tanhf(v0);
                    o.y = r2.y + DT_INL * tanhf(v1);
                } else {
                    o.x = v0; o.y = v1;
                    if (rp) {
                        const float2 r2 = *(const float2*)(rp + (size_t)m * ldr + n);
                        o.x += r2.x; o.y += r2.y;
                    }
                }
                *(float2*)(C + (size_t)m * ldc + n) = o;
                if (so) {
                    __nv_bfloat162 h2, l2;
                    split2(o.x, o.y, h2, l2);
                    __nv_bfloat16* sp = so + (size_t)m * KTRIP + n;
                    *(__nv_bfloat162*)(sp)           = h2;   // hi
                    *(__nv_bfloat162*)(sp + CCH)     = h2;   // hi
                    *(__nv_bfloat162*)(sp + 2 * CCH) = l2;   // lo
                }
            }
        }
    }
}

// ---------------------------------------------------------------------------
// Launch
// ---------------------------------------------------------------------------
extern "C" void kernel_launch(void* const* d_in, const int* in_sizes, int n_in,
                              void* d_out, int out_size)
{
    const float* x        = (const float*)d_in[0];
    const float* gn_scale = (const float*)d_in[1];
    const float* gn_bias  = (const float*)d_in[2];
    const float* qkv_w    = (const float*)d_in[3];
    const float* qkv_b    = (const float*)d_in[4];
    const float* proj_w   = (const float*)d_in[5];
    const float* proj_b   = (const float*)d_in[6];
    const float* inl_w    = (const float*)d_in[7];
    const float* inl_b    = (const float*)d_in[8];
    float* out = (float*)d_out;

    float *ht, *qkvbuf, *hf, *Sb;
    __nv_bfloat16 *ht2, *hf2, *wq2, *wi2, *wp2, *Pb, *Qh, *Kh, *Vt;
    cudaGetSymbolAddress((void**)&ht,     g_ht);
    cudaGetSymbolAddress((void**)&qkvbuf, g_qkv);
    cudaGetSymbolAddress((void**)&hf,     g_hf);
    cudaGetSymbolAddress((void**)&Sb,     g_S);
    cudaGetSymbolAddress((void**)&Pb,     g_P);
    cudaGetSymbolAddress((void**)&Qh,     g_qh);
    cudaGetSymbolAddress((void**)&Kh,     g_kh);
    cudaGetSymbolAddress((void**)&Vt,     g_vt);
    cudaGetSymbolAddress((void**)&ht2,    g_ht2);
    cudaGetSymbolAddress((void**)&hf2,    g_hf2);
    cudaGetSymbolAddress((void**)&wq2,    g_wq2);
    cudaGetSymbolAddress((void**)&wi2,    g_wi2);
    cudaGetSymbolAddress((void**)&wp2,    g_wp2);

    const long SC  = (long)SSP * CCH;         // 524288
    const long SK  = (long)SSP * KTRIP;       // per-b split stride
    const long S3C = (long)SSP * THREE_C;

    // 1) GroupNorm -> ht [B,S,C]
    gn_kernel<<<BATCH * NG, 256>>>(x, gn_scale, gn_bias, ht);

    // 2) conversions: ht2 A-pattern (GEMM A-operand), weights
    conv_split<<<(BATCH * SSP * CCH / 4) / 256, 256>>>(ht, ht2, 0);      // A
    conv_split<<<(THREE_C * CCH / 4) / 256, 256>>>(qkv_w, wq2, 1);       // B
    conv_split<<<(CCH * CCH / 4) / 256, 256>>>(inl_w, wi2, 1);           // B
    conv_split<<<(CCH * CCH / 4) / 256, 256>>>(proj_w, wp2, 0);          // A

    // 3) QKV: qkv[b][s][o] = ht[b][s] . wq[o]  (M=S, N=3C)
    mm_mma<128,128,2><<<dim3(THREE_C/128, SSP/128, BATCH), 256>>>(
        ht2, KTRIP, SK,  wq2, KTRIP, 0L,
        qkvbuf, THREE_C, 1, S3C, 0L,
        nullptr, qkv_b, nullptr, 0, 0L, 0,
        nullptr, 0L, 0L,
        KTRIP, (long)KTRIP, 0L, 0L, 0L, 0L);

    // 4) per-head Q/K split + V transpose-split
    qk_conv<<<dim3(64, 1, NBH), 256>>>(qkvbuf, Qh, Kh);
    v_conv<<<dim3(8, 1, NBH), 256>>>(qkvbuf, Vt);

    // 5) S = (Q/8) K^T  per (b,h): M=N=1024, K'=192
    mm_mma<128,128,2><<<dim3(SSP/128, SSP/128, NBH), 256>>>(
        Qh, 192, (long)SSP*192,  Kh, 192, (long)SSP*192,
        Sb, SSP, 1, (long)SSP*SSP, 0L,
        nullptr, nullptr, nullptr, 0, 0L, 0,
        nullptr, 0L, 0L,
        192, 192L, 0L, 0L, 0L, 0L);

    // 6) softmax -> P (p_hi | p_lo)
    softmax_k<<<NBH * SSP / 8, 256>>>(Sb, Pb);

    // 7) O = P V   (3-term split via K-segment mapping, K''=3072)
    //    writes hf [B][S][C] slice (cols h*64..) and hf2 split (pattern A)
    mm_mma<128,64,4><<<dim3(1, SSP/128, NBH), 256>>>(
        Pb, 2048, (long)SSP*2048,  Vt, 2048, (long)HD*2048,
        hf, CCH, NH, SC, 64L,
        nullptr, nullptr, nullptr, 0, 0L, 0,
        hf2, SK, 64L,
        3072, 1024L, -1024L, -1024L, 0L, -2048L);

    // 8) INL x3: hf <- hf + dt*tanh(hf @ inl_w^T + b); fused split-out for next iter
    for (int it = 0; it < 3; it++) {
        mm_mma<128,128,2><<<dim3(CCH/128, SSP/128, BATCH), 256>>>(
            hf2, KTRIP, SK,  wi2, KTRIP, 0L,
            hf, CCH, 1, SC, 0L,
            nullptr, inl_b, hf, CCH, SC, 1,
            (it < 2) ? hf2 : nullptr, SK, 0L,
            KTRIP, (long)KTRIP, 0L, 0L, 0L, 0L);
    }

    // 9) proj conv (B-pattern) + proj GEMM: out[b][c][s] = proj_w[c] . hf[b][s] + x
    conv_split<<<(BATCH * SSP * CCH / 4) / 256, 256>>>(hf, hf2, 1);      // B
    mm_mma<128,128,2><<<dim3(SSP/128, CCH/128, BATCH), 256>>>(
        wp2, KTRIP, 0L,  hf2, KTRIP, SK,
        out, SSP, 1, SC, 0L,
        proj_b, nullptr, x, SSP, SC, 0,
        nullptr, 0L, 0L,
        KTRIP, (long)KTRIP, 0L, 0L, 0L, 0L);
}

// round 9
// speedup vs baseline: 2.1723x; 1.3308x over previous
#include <cuda_runtime.h>
#include <cuda_bf16.h>
#include <math.h>
#include <stdint.h>

// Problem constants
#define BATCH 8
#define CCH   512
#define SSP   1024
#define NG    8
#define CPG   64
#define NH    8
#define HD    64
#define THREE_C 1536
#define EPS_GN 1e-5f
#define DT_INL 0.1f

#define KTRIP  1536        // 3 * CCH (split-precision concatenated K)
#define NBH    64          // BATCH * NH

// ---------------------------------------------------------------------------
// Scratch (device globals)
// ---------------------------------------------------------------------------
__device__ __align__(1024) float g_ht [BATCH * SSP * CCH];
__device__ __align__(1024) float g_qkv[BATCH * SSP * THREE_C];     // [B][S][3C]
__device__ __align__(1024) float g_hf [BATCH * SSP * CCH];
__device__ __align__(1024) __nv_bfloat16 g_qh [NBH * SSP * 192];   // Q split (A)
__device__ __align__(1024) __nv_bfloat16 g_kh [NBH * SSP * 192];   // K split (B)
__device__ __align__(1024) __nv_bfloat16 g_vt [NBH * HD * 2048];   // V^T hi|lo
__device__ __align__(1024) __nv_bfloat16 g_ht2 [BATCH * SSP * KTRIP];
__device__ __align__(1024) __nv_bfloat16 g_hf2 [BATCH * SSP * KTRIP];
__device__ __align__(1024) __nv_bfloat16 g_wq2 [THREE_C * KTRIP];
__device__ __align__(1024) __nv_bfloat16 g_wi2 [CCH * KTRIP];
__device__ __align__(1024) __nv_bfloat16 g_wp2 [CCH * KTRIP];

// ---------------------------------------------------------------------------
// PTX helpers
// ---------------------------------------------------------------------------
__device__ __forceinline__ uint32_t smem_u32(const void* p) {
    uint32_t a;
    asm("{ .reg .u64 t; cvta.to.shared.u64 t, %1; cvt.u32.u64 %0, t; }" : "=r"(a) : "l"(p));
    return a;
}
__device__ __forceinline__ void cpasync16(uint32_t s, const void* g) {
    asm volatile("cp.async.cg.shared.global [%0], [%1], 16;" :: "r"(s), "l"(g));
}
#define CP_COMMIT() asm volatile("cp.async.commit_group;" ::: "memory")
#define CP_WAIT0()  asm volatile("cp.async.wait_group 0;" ::: "memory")

#define LDSM_X4(r0, r1, r2, r3, a) \
    asm volatile("ldmatrix.sync.aligned.m8n8.x4.shared.b16 {%0,%1,%2,%3}, [%4];" \
        : "=r"(r0), "=r"(r1), "=r"(r2), "=r"(r3) : "r"(a))

__device__ __forceinline__ void mma16816(float* d,
    uint32_t a0, uint32_t a1, uint32_t a2, uint32_t a3,
    uint32_t b0, uint32_t b1)
{
    asm volatile(
        "mma.sync.aligned.m16n8k16.row.col.f32.bf16.bf16.f32 "
        "{%0,%1,%2,%3}, {%4,%5,%6,%7}, {%8,%9}, {%0,%1,%2,%3};"
        : "+f"(d[0]), "+f"(d[1]), "+f"(d[2]), "+f"(d[3])
        : "r"(a0), "r"(a1), "r"(a2), "r"(a3), "r"(b0), "r"(b1));
}

__device__ __forceinline__ void split2(float x, float y,
    __nv_bfloat162& h2, __nv_bfloat162& l2)
{
    h2.x = __float2bfloat16(x); h2.y = __float2bfloat16(y);
    l2.x = __float2bfloat16(x - __bfloat162float(h2.x));
    l2.y = __float2bfloat16(y - __bfloat162float(h2.y));
}
__device__ __forceinline__ void split_pack(float x, float y,
    uint32_t& hi, uint32_t& lo)
{
    __nv_bfloat162 h2, l2;
    split2(x, y, h2, l2);
    hi = *(uint32_t*)&h2;
    lo = *(uint32_t*)&l2;
}

// ---------------------------------------------------------------------------
// GroupNorm + transpose to [B, S, C]
// ---------------------------------------------------------------------------
__global__ __launch_bounds__(256) void gn_kernel(
    const float* __restrict__ x, const float* __restrict__ scale,
    const float* __restrict__ bias, float* __restrict__ ht)
{
    const int b = blockIdx.x / NG;
    const int g = blockIdx.x % NG;
    const float* xp = x + ((size_t)b * CCH + (size_t)g * CPG) * SSP;
    const int NEL = CPG * SSP;

    float s = 0.f, s2 = 0.f;
    for (int i = threadIdx.x; i < NEL; i += 256) {
        float v = xp[i];
        s += v; s2 += v * v;
    }
    #pragma unroll
    for (int o = 16; o > 0; o >>= 1) {
        s  += __shfl_down_sync(0xffffffffu, s,  o);
        s2 += __shfl_down_sync(0xffffffffu, s2, o);
    }
    __shared__ float ws[8], ws2[8];
    __shared__ float sh_mean, sh_inv;
    const int wid = threadIdx.x >> 5, lane = threadIdx.x & 31;
    if (lane == 0) { ws[wid] = s; ws2[wid] = s2; }
    __syncthreads();
    if (threadIdx.x == 0) {
        float S = 0.f, S2 = 0.f;
        #pragma unroll
        for (int w = 0; w < 8; w++) { S += ws[w]; S2 += ws2[w]; }
        float mean = S / (float)NEL;
        float var  = S2 / (float)NEL - mean * mean;
        sh_mean = mean;
        sh_inv  = rsqrtf(var + EPS_GN);
    }
    __syncthreads();
    const float mean = sh_mean, inv = sh_inv;
    for (int i = threadIdx.x; i < NEL; i += 256) {
        int c    = g * CPG + (i / SSP);
        int spos = i % SSP;
        float v = (xp[i] - mean) * inv * scale[c] + bias[c];
        ht[((size_t)b * SSP + spos) * CCH + c] = v;
    }
}

// ---------------------------------------------------------------------------
// Split-precision conversion: fp32 [rows,512] -> bf16 [rows,1536]
// pattern A (pb=0): [hi | hi | lo], pattern B (pb=1): [hi | lo | hi]
// ---------------------------------------------------------------------------
__global__ __launch_bounds__(256) void conv_split(
    const float* __restrict__ in, __nv_bfloat16* __restrict__ out, int pb)
{
    int i = blockIdx.x * 256 + threadIdx.x;
    int r = i >> 7;
    int c = (i & 127) << 2;
    float4 v = ((const float4*)in)[i];
    __nv_bfloat162 h0, h1, l0, l1;
    split2(v.x, v.y, h0, l0);
    split2(v.z, v.w, h1, l1);
    __nv_bfloat162* o = (__nv_bfloat162*)(out + (size_t)r * KTRIP + c);
    o[0] = h0; o[1] = h1;
    __nv_bfloat162* o1 = o + (CCH >> 1);
    __nv_bfloat162* o2 = o + (CCH);
    if (pb) { o1[0] = l0; o1[1] = l1; o2[0] = h0; o2[1] = h1; }
    else    { o1[0] = h0; o1[1] = h1; o2[0] = l0; o2[1] = l1; }
}

// ---------------------------------------------------------------------------
// Q/K per-head split conversion from qkv [B][S][3C]
// ---------------------------------------------------------------------------
__global__ __launch_bounds__(256) void qk_conv(
    const float* __restrict__ qkv, __nv_bfloat16* __restrict__ Qh,
    __nv_bfloat16* __restrict__ Kh)
{
    const int z = blockIdx.z;
    const int b = z >> 3, h = z & 7;
    const int s = blockIdx.x * 16 + (threadIdx.x >> 4);
    const int c4 = threadIdx.x & 15;

    const float* base = qkv + ((size_t)b * SSP + s) * THREE_C + h * HD + c4 * 4;
    // Q (pattern A, pre-scaled)
    {
        float4 v = *(const float4*)base;
        v.x *= 0.125f; v.y *= 0.125f; v.z *= 0.125f; v.w *= 0.125f;
        __nv_bfloat162 h0, h1, l0, l1;
        split2(v.x, v.y, h0, l0);
        split2(v.z, v.w, h1, l1);
        __nv_bfloat162* o = (__nv_bfloat162*)(Qh + ((size_t)z * SSP + s) * 192 + c4 * 4);
        o[0] = h0; o[1] = h1;
        o[32] = h0; o[33] = h1;
        o[64] = l0; o[65] = l1;
    }
    // K (pattern B)
    {
        float4 v = *(const float4*)(base + CCH);
        __nv_bfloat162 h0, h1, l0, l1;
        split2(v.x, v.y, h0, l0);
        split2(v.z, v.w, h1, l1);
        __nv_bfloat162* o = (__nv_bfloat162*)(Kh + ((size_t)z * SSP + s) * 192 + c4 * 4);
        o[0] = h0; o[1] = h1;
        o[32] = l0; o[33] = l1;
        o[64] = h0; o[65] = h1;
    }
}

// ---------------------------------------------------------------------------
// V transpose + split: qkv -> Vt [z][d][ v_hi(1024) | v_lo(1024) ]
// ---------------------------------------------------------------------------
__global__ __launch_bounds__(256) void v_conv(
    const float* __restrict__ qkv, __nv_bfloat16* __restrict__ Vt)
{
    const int z = blockIdx.z;
    const int b = z >> 3, h = z & 7;
    const int tt = blockIdx.x * 128;
    __shared__ float ts[128][65];

    const float* src = qkv + ((size_t)b * SSP + tt) * THREE_C + 2 * CCH + h * HD;
    #pragma unroll
    for (int u = 0; u < 8; u++) {
        int i = u * 256 + threadIdx.x;
        int r = i >> 4, c4 = i & 15;
        float4 v = *(const float4*)(src + (size_t)r * THREE_C + c4 * 4);
        ts[r][c4 * 4 + 0] = v.x; ts[r][c4 * 4 + 1] = v.y;
        ts[r][c4 * 4 + 2] = v.z; ts[r][c4 * 4 + 3] = v.w;
    }
    __syncthreads();
    #pragma unroll
    for (int u = 0; u < 8; u++) {
        int i = u * 256 + threadIdx.x;
        int d = i >> 5, t4 = (i & 31) * 4;
        float v0 = ts[t4 + 0][d], v1 = ts[t4 + 1][d];
        float v2 = ts[t4 + 2][d], v3 = ts[t4 + 3][d];
        __nv_bfloat162 h0, h1, l0, l1;
        split2(v0, v1, h0, l0);
        split2(v2, v3, h1, l1);
        __nv_bfloat16* o = Vt + ((size_t)z * HD + d) * 2048 + tt + t4;
        *(__nv_bfloat162*)(o)          = h0;
        *(__nv_bfloat162*)(o + 2)      = h1;
        *(__nv_bfloat162*)(o + 1024)   = l0;
        *(__nv_bfloat162*)(o + 1026)   = l1;
    }
}

// ---------------------------------------------------------------------------
// Fused flash attention (FA2-style, HMMA bf16, split-precision).
// grid (S/128, NBH), 256 thr. Warp w owns q rows q0 + w*16 .. +15, all 64 dims.
// Reads Qh/Kh (192-k split, Q pre-scaled) and Vt (hi|lo).
// Writes hf [B][S][C] head slice + hf2 split (pattern A).
// ---------------------------------------------------------------------------
#define FT_KS   25600                   // K stage: 64 rows * 400 B
#define FT_VS   18432                   // V stage: hi+lo, 64 rows * 144 B each
#define FT_SMEM (2*FT_KS + 2*FT_VS)     // 88064

__global__ __launch_bounds__(256) void fattn(
    const __nv_bfloat16* __restrict__ Qh, const __nv_bfloat16* __restrict__ Kh,
    const __nv_bfloat16* __restrict__ Vt, float* __restrict__ hf,
    __nv_bfloat16* __restrict__ hf2)
{
    extern __shared__ __align__(16) char sm[];
    const uint32_t s0 = smem_u32(sm);
    const uint32_t Kst[2] = { s0, s0 + FT_KS };
    const uint32_t Vst[2] = { s0 + 2 * FT_KS, s0 + 2 * FT_KS + FT_VS };

    const int tid = threadIdx.x, wid = tid >> 5, lane = tid & 31;
    const int z = blockIdx.y, b = z >> 3, h = z & 7;
    const int q0 = blockIdx.x * 128;

    const __nv_bfloat16* Qz = Qh + (size_t)z * SSP * 192;
    const __nv_bfloat16* Kz = Kh + (size_t)z * SSP * 192;
    const __nv_bfloat16* Vz = Vt + (size_t)z * HD * 2048;

    // Q fragments in registers (12 k16-steps x 4 regs)
    uint32_t qf[12][4];
    {
        const int r = q0 + wid * 16 + (lane >> 2);
        const __nv_bfloat16* q_r0 = Qz + (size_t)r * 192 + (lane & 3) * 2;
        const __nv_bfloat16* q_r1 = q_r0 + 8 * 192;
        #pragma unroll
        for (int ks = 0; ks < 12; ks++) {
            qf[ks][0] = *(const uint32_t*)(q_r0 + ks * 16);
            qf[ks][1] = *(const uint32_t*)(q_r1 + ks * 16);
            qf[ks][2] = *(const uint32_t*)(q_r0 + ks * 16 + 8);
            qf[ks][3] = *(const uint32_t*)(q_r1 + ks * 16 + 8);
        }
    }

    auto load_kv = [&](int kt, uint32_t Ks, uint32_t Vs) {
        #pragma unroll
        for (int u = 0; u < 6; u++) {               // K: 64 rows x 24 chunks
            int i = u * 256 + tid;
            int r = i / 24, c = i - r * 24;
            cpasync16(Ks + r * 400 + c * 16, Kz + (size_t)(kt + r) * 192 + c * 8);
        }
        #pragma unroll
        for (int u = 0; u < 2; u++) {               // V hi/lo: 64 rows x 8 chunks
            int i = u * 256 + tid;
            int d = i >> 3, c = i & 7;
            cpasync16(Vs + d * 144 + c * 16,
                      Vz + (size_t)d * 2048 + kt + c * 8);
            cpasync16(Vs + 9216 + d * 144 + c * 16,
                      Vz + (size_t)d * 2048 + 1024 + kt + c * 8);
        }
    };

    load_kv(0, Kst[0], Vst[0]);
    CP_COMMIT();

    float o[8][4];
    #pragma unroll
    for (int i = 0; i < 8; i++)
        #pragma unroll
        for (int j = 0; j < 4; j++) o[i][j] = 0.f;
    float m0 = -INFINITY, m1 = -INFINITY, l0 = 0.f, l1 = 0.f;

    const uint32_t kb_l = ((lane & 7) + ((lane >> 4) & 1) * 8) * 400
                        + (((lane >> 3) & 1) << 4);
    const uint32_t vb_l = ((lane & 7) + ((lane >> 4) & 1) * 8) * 144
                        + (((lane >> 3) & 1) << 4);

    for (int t = 0; t < 16; t++) {
        CP_WAIT0();
        __syncthreads();
        if (t < 15) {
            load_kv((t + 1) * 64, Kst[(t + 1) & 1], Vst[(t + 1) & 1]);
            CP_COMMIT();
        }
        const uint32_t Ks = Kst[t & 1];
        const uint32_t Vs = Vst[t & 1];

        // ---- S = Q K^T (64-key tile) ----
        float s[8][4];
        #pragma unroll
        for (int i = 0; i < 8; i++)
            #pragma unroll
            for (int j = 0; j < 4; j++) s[i][j] = 0.f;
        #pragma unroll
        for (int ks = 0; ks < 12; ks++) {
            uint32_t kf[4][4];
            #pragma unroll
            for (int g = 0; g < 4; g++)
                LDSM_X4(kf[g][0], kf[g][1], kf[g][2], kf[g][3],
                        Ks + kb_l + g * (16 * 400) + ks * 32);
            #pragma unroll
            for (int j = 0; j < 8; j++)
                mma16816(s[j], qf[ks][0], qf[ks][1], qf[ks][2], qf[ks][3],
                         kf[j >> 1][(j & 1) * 2], kf[j >> 1][(j & 1) * 2 + 1]);
        }

        // ---- online softmax ----
        float mx0 = s[0][0], mx1 = s[0][2];
        #pragma unroll
        for (int j = 0; j < 8; j++) {
            mx0 = fmaxf(mx0, fmaxf(s[j][0], s[j][1]));
            mx1 = fmaxf(mx1, fmaxf(s[j][2], s[j][3]));
        }
        mx0 = fmaxf(mx0, __shfl_xor_sync(0xffffffffu, mx0, 1));
        mx0 = fmaxf(mx0, __shfl_xor_sync(0xffffffffu, mx0, 2));
        mx1 = fmaxf(mx1, __shfl_xor_sync(0xffffffffu, mx1, 1));
        mx1 = fmaxf(mx1, __shfl_xor_sync(0xffffffffu, mx1, 2));
        const float mn0 = fmaxf(m0, mx0), mn1 = fmaxf(m1, mx1);
        const float sc0 = __expf(m0 - mn0), sc1 = __expf(m1 - mn1);
        m0 = mn0; m1 = mn1;
        l0 *= sc0; l1 *= sc1;
        #pragma unroll
        for (int j = 0; j < 8; j++) {
            o[j][0] *= sc0; o[j][1] *= sc0;
            o[j][2] *= sc1; o[j][3] *= sc1;
        }
        #pragma unroll
        for (int j = 0; j < 8; j++) {
            s[j][0] = __expf(s[j][0] - mn0); s[j][1] = __expf(s[j][1] - mn0);
            s[j][2] = __expf(s[j][2] - mn1); s[j][3] = __expf(s[j][3] - mn1);
            l0 += s[j][0] + s[j][1];
            l1 += s[j][2] + s[j][3];
        }

        // ---- P fragments (C->A layout identity, hi/lo split) ----
        uint32_t phi[4][4], plo[4][4];
        #pragma unroll
        for (int f = 0; f < 4; f++) {
            split_pack(s[2*f  ][0], s[2*f  ][1], phi[f][0], plo[f][0]);
            split_pack(s[2*f  ][2], s[2*f  ][3], phi[f][1], plo[f][1]);
            split_pack(s[2*f+1][0], s[2*f+1][1], phi[f][2], plo[f][2]);
            split_pack(s[2*f+1][2], s[2*f+1][3], phi[f][3], plo[f][3]);
        }

        // ---- O += P V (3-term split) ----
        #pragma unroll
        for (int f = 0; f < 4; f++) {
            uint32_t vb[4][4];
            #pragma unroll
            for (int g = 0; g < 4; g++)
                LDSM_X4(vb[g][0], vb[g][1], vb[g][2], vb[g][3],
                        Vs + vb_l + g * (16 * 144) + f * 32);
            #pragma unroll
            for (int j = 0; j < 8; j++) {
                mma16816(o[j], phi[f][0], phi[f][1], phi[f][2], phi[f][3],
                         vb[j >> 1][(j & 1) * 2], vb[j >> 1][(j & 1) * 2 + 1]);
                mma16816(o[j], plo[f][0], plo[f][1], plo[f][2], plo[f][3],
                         vb[j >> 1][(j & 1) * 2], vb[j >> 1][(j & 1) * 2 + 1]);
            }
            #pragma unroll
            for (int g = 0; g < 4; g++)
                LDSM_X4(vb[g][0], vb[g][1], vb[g][2], vb[g][3],
                        Vs + 9216 + vb_l + g * (16 * 144) + f * 32);
            #pragma unroll
            for (int j = 0; j < 8; j++)
                mma16816(o[j], phi[f][0], phi[f][1], phi[f][2], phi[f][3],
                         vb[j >> 1][(j & 1) * 2], vb[j >> 1][(j & 1) * 2 + 1]);
        }
    }

    // ---- epilogue ----
    l0 += __shfl_xor_sync(0xffffffffu, l0, 1);
    l0 += __shfl_xor_sync(0xffffffffu, l0, 2);
    l1 += __shfl_xor_sync(0xffffffffu, l1, 1);
    l1 += __shfl_xor_sync(0xffffffffu, l1, 2);
    const float inv0 = 1.f / l0, inv1 = 1.f / l1;

    const int r0 = q0 + wid * 16 + (lane >> 2);
    #pragma unroll
    for (int j = 0; j < 8; j++) {
        const int col = h * HD + j * 8 + (lane & 3) * 2;
        #pragma unroll
        for (int hh = 0; hh < 2; hh++) {
            const int r = r0 + hh * 8;
            const float inv = hh ? inv1 : inv0;
            float2 v;
            v.x = o[j][hh * 2 + 0] * inv;
            v.y = o[j][hh * 2 + 1] * inv;
            *(float2*)(hf + ((size_t)b * SSP + r) * CCH + col) = v;
            __nv_bfloat162 h2, l2;
            split2(v.x, v.y, h2, l2);
            __nv_bfloat16* sp = hf2 + (size_t)b * SSP * KTRIP + (size_t)r * KTRIP + col;
            *(__nv_bfloat162*)(sp)           = h2;
            *(__nv_bfloat162*)(sp + CCH)     = h2;
            *(__nv_bfloat162*)(sp + 2 * CCH) = l2;
        }
    }
}

// ---------------------------------------------------------------------------
// Templated HMMA bf16 GEMM (dense layers)
// ---------------------------------------------------------------------------
template<int MT_, int NT_, int WM_>
__global__ __launch_bounds__(256) void mm_mma(
    const __nv_bfloat16* __restrict__ A, long lda, long sA,
    const __nv_bfloat16* __restrict__ B, long ldb, long sB,
    float* __restrict__ C, int ldc, int zdiv, long sC1, long sC2,
    const float* __restrict__ biasM, const float* __restrict__ biasN,
    const float* __restrict__ resid, int ldr, long sR1,
    int tanh_mode,
    __nv_bfloat16* __restrict__ sout, long sO1, long sO2,
    int kTot)
{
    constexpr int WN_ = 8 / WM_;
    constexpr int WTM = MT_ / WM_;
    constexpr int WTN = NT_ / WN_;
    constexpr int MI  = WTM / 16;
    constexpr int NI  = WTN / 8;
    constexpr int NI2 = WTN / 16;

    __shared__ __align__(16) __nv_bfloat16 As[2][MT_][40];
    __shared__ __align__(16) __nv_bfloat16 Bs[2][NT_][40];

    const int tid  = threadIdx.x;
    const int wid  = tid >> 5;
    const int lane = tid & 31;
    const int wm   = wid % WM_;
    const int wn   = wid / WM_;

    const int bb = blockIdx.z;
    const int zo = bb / zdiv, zi = bb % zdiv;
    A += (size_t)bb * sA;
    B += (size_t)bb * sB;
    C += (size_t)zo * sC1 + (size_t)zi * sC2;
    const float* rp = resid ? (resid + (size_t)zo * sR1) : nullptr;
    __nv_bfloat16* so = sout ? (sout + (size_t)zo * sO1 + (size_t)zi * sO2) : nullptr;
    const int m0 = blockIdx.y * MT_;
    const int n0 = blockIdx.x * NT_;

    const uint32_t sa0 = smem_u32(&As[0][0][0]);
    const uint32_t sb0 = smem_u32(&Bs[0][0][0]);
    const uint32_t STGA = MT_ * 80;
    const uint32_t STGB = NT_ * 80;

    float acc[MI][NI][4];
    #pragma unroll
    for (int mi = 0; mi < MI; mi++)
        #pragma unroll
        for (int ni = 0; ni < NI; ni++)
            #pragma unroll
            for (int r = 0; r < 4; r++) acc[mi][ni][r] = 0.f;

    auto load_stage = [&](int it, int st) {
        long k0 = (long)it * 32;
        const __nv_bfloat16* Ak = A + k0;
        const __nv_bfloat16* Bk = B + k0;
        uint32_t _sa = sa0 + st * STGA;
        uint32_t _sb = sb0 + st * STGB;
        #pragma unroll
        for (int i = tid; i < MT_ * 4; i += 256) {
            int r = i >> 2, c = i & 3;
            cpasync16(_sa + r * 80 + c * 16, Ak + (size_t)(m0 + r) * lda + c * 8);
        }
        #pragma unroll
        for (int i = tid; i < NT_ * 4; i += 256) {
            int r = i >> 2, c = i & 3;
            cpasync16(_sb + r * 80 + c * 16, Bk + (size_t)(n0 + r) * ldb + c * 8);
        }
    };

    const int NIT = kTot / 32;
    load_stage(0, 0);
    CP_COMMIT();

    const uint32_t a_lbase = (wm * WTM + (lane & 15)) * 80 + ((lane >> 4) << 4);
    const uint32_t b_lbase = (wn * WTN + (lane & 7) + ((lane >> 4) & 1) * 8) * 80
                           + (((lane >> 3) & 1) << 4);

    for (int it = 0; it < NIT; it++) {
        CP_WAIT0();
        __syncthreads();
        if (it + 1 < NIT) {
            load_stage(it + 1, (it + 1) & 1);
            CP_COMMIT();
        }
        const int st = it & 1;
        const uint32_t sa = sa0 + st * STGA;
        const uint32_t sb = sb0 + st * STGB;

        #pragma unroll
        for (int kp = 0; kp < 2; kp++) {
            uint32_t af[MI][4];
            #pragma unroll
            for (int mi = 0; mi < MI; mi++)
                LDSM_X4(af[mi][0], af[mi][1], af[mi][2], af[mi][3],
                        sa + a_lbase + mi * (16 * 80) + kp * 32);
            uint32_t bf[NI2][4];
            #pragma unroll
            for (int pi = 0; pi < NI2; pi++)
                LDSM_X4(bf[pi][0], bf[pi][1], bf[pi][2], bf[pi][3],
                        sb + b_lbase + pi * (16 * 80) + kp * 32);
            #pragma unroll
            for (int mi = 0; mi < MI; mi++)
                #pragma unroll
                for (int ni = 0; ni < NI; ni++)
                    mma16816(acc[mi][ni],
                             af[mi][0], af[mi][1], af[mi][2], af[mi][3],
                             bf[ni >> 1][(ni & 1) * 2],
                             bf[ni >> 1][(ni & 1) * 2 + 1]);
        }
        __syncthreads();
    }

    // Epilogue
    const int mb = m0 + wm * WTM;
    const int nb = n0 + wn * WTN;
    const int rbase = lane >> 2;
    const int cbase = (lane & 3) * 2;
    #pragma unroll
    for (int mi = 0; mi < MI; mi++) {
        #pragma unroll
        for (int h = 0; h < 2; h++) {
            const int m = mb + mi * 16 + rbase + h * 8;
            const float bm = biasM ? biasM[m] : 0.f;
            #pragma unroll
            for (int ni = 0; ni < NI; ni++) {
                const int n = nb + ni * 8 + cbase;
                float v0 = acc[mi][ni][h * 2 + 0] + bm;
                float v1 = acc[mi][ni][h * 2 + 1] + bm;
                if (biasN) { v0 += biasN[n]; v1 += biasN[n + 1]; }
                float2 o;
                if (tanh_mode) {
                    const float2 r2 = *(const float2*)(rp + (size_t)m * ldr + n);
                    o.x = r2.x + DT_INL * tanhf(v0);
                    o.y = r2.y + DT_INL * tanhf(v1);
                } else {
                    o.x = v0; o.y = v1;
                    if (rp) {
                        const float2 r2 = *(const float2*)(rp + (size_t)m * ldr + n);
                        o.x += r2.x; o.y += r2.y;
                    }
                }
                *(float2*)(C + (size_t)m * ldc + n) = o;
                if (so) {
                    __nv_bfloat162 h2, l2;
                    split2(o.x, o.y, h2, l2);
                    __nv_bfloat16* sp = so + (size_t)m * KTRIP + n;
                    *(__nv_bfloat162*)(sp)           = h2;
                    *(__nv_bfloat162*)(sp + CCH)     = h2;
                    *(__nv_bfloat162*)(sp + 2 * CCH) = l2;
                }
            }
        }
    }
}

// ---------------------------------------------------------------------------
// Launch
// ---------------------------------------------------------------------------
extern "C" void kernel_launch(void* const* d_in, const int* in_sizes, int n_in,
                              void* d_out, int out_size)
{
    const float* x        = (const float*)d_in[0];
    const float* gn_scale = (const float*)d_in[1];
    const float* gn_bias  = (const float*)d_in[2];
    const float* qkv_w    = (const float*)d_in[3];
    const float* qkv_b    = (const float*)d_in[4];
    const float* proj_w   = (const float*)d_in[5];
    const float* proj_b   = (const float*)d_in[6];
    const float* inl_w    = (const float*)d_in[7];
    const float* inl_b    = (const float*)d_in[8];
    float* out = (float*)d_out;

    float *ht, *qkvbuf, *hf;
    __nv_bfloat16 *ht2, *hf2, *wq2, *wi2, *wp2, *Qh, *Kh, *Vt;
    cudaGetSymbolAddress((void**)&ht,     g_ht);
    cudaGetSymbolAddress((void**)&qkvbuf, g_qkv);
    cudaGetSymbolAddress((void**)&hf,     g_hf);
    cudaGetSymbolAddress((void**)&Qh,     g_qh);
    cudaGetSymbolAddress((void**)&Kh,     g_kh);
    cudaGetSymbolAddress((void**)&Vt,     g_vt);
    cudaGetSymbolAddress((void**)&ht2,    g_ht2);
    cudaGetSymbolAddress((void**)&hf2,    g_hf2);
    cudaGetSymbolAddress((void**)&wq2,    g_wq2);
    cudaGetSymbolAddress((void**)&wi2,    g_wi2);
    cudaGetSymbolAddress((void**)&wp2,    g_wp2);

    cudaFuncSetAttribute(fattn, cudaFuncAttributeMaxDynamicSharedMemorySize, FT_SMEM);

    const long SC  = (long)SSP * CCH;
    const long SK  = (long)SSP * KTRIP;
    const long S3C = (long)SSP * THREE_C;

    // 1) GroupNorm -> ht [B,S,C]
    gn_kernel<<<BATCH * NG, 256>>>(x, gn_scale, gn_bias, ht);

    // 2) conversions
    conv_split<<<(BATCH * SSP * CCH / 4) / 256, 256>>>(ht, ht2, 0);      // A
    conv_split<<<(THREE_C * CCH / 4) / 256, 256>>>(qkv_w, wq2, 1);       // B
    conv_split<<<(CCH * CCH / 4) / 256, 256>>>(inl_w, wi2, 1);           // B
    conv_split<<<(CCH * CCH / 4) / 256, 256>>>(proj_w, wp2, 0);          // A

    // 3) QKV: qkv[b][s][o] = ht[b][s] . wq[o]
    mm_mma<128,128,2><<<dim3(THREE_C/128, SSP/128, BATCH), 256>>>(
        ht2, KTRIP, SK,  wq2, KTRIP, 0L,
        qkvbuf, THREE_C, 1, S3C, 0L,
        nullptr, qkv_b, nullptr, 0, 0L, 0,
        nullptr, 0L, 0L, KTRIP);

    // 4) per-head Q/K split + V transpose-split
    qk_conv<<<dim3(64, 1, NBH), 256>>>(qkvbuf, Qh, Kh);
    v_conv<<<dim3(8, 1, NBH), 256>>>(qkvbuf, Vt);

    // 5) fused flash attention -> hf + hf2 (pattern A)
    fattn<<<dim3(SSP/128, NBH), 256, FT_SMEM>>>(Qh, Kh, Vt, hf, hf2);

    // 6) INL x3: hf <- hf + dt*tanh(hf @ inl_w^T + b); fused split-out
    for (int it = 0; it < 3; it++) {
        mm_mma<128,128,2><<<dim3(CCH/128, SSP/128, BATCH), 256>>>(
            hf2, KTRIP, SK,  wi2, KTRIP, 0L,
            hf, CCH, 1, SC, 0L,
            nullptr, inl_b, hf, CCH, SC, 1,
            (it < 2) ? hf2 : nullptr, SK, 0L, KTRIP);
    }

    // 7) proj conv (B-pattern) + proj GEMM with residual
    conv_split<<<(BATCH * SSP * CCH / 4) / 256, 256>>>(hf, hf2, 1);      // B
    mm_mma<128,128,2><<<dim3(SSP/128, CCH/128, BATCH), 256>>>(
        wp2, KTRIP, 0L,  hf2, KTRIP, SK,
        out, SSP, 1, SC, 0L,
        proj_b, nullptr, x, SSP, SC, 0,
        nullptr, 0L, 0L, KTRIP);
}